// round 1
// baseline (speedup 1.0000x reference)
#include <cuda_runtime.h>
#include <math.h>

#define C   128
#define HW  1024
#define NB  4
#define N   4096
#define K   128
#define INV_TEMP (1.0f/0.07f)

// Scratch: normalized, transposed-to-row-major [N, C] features. 2 MB each.
__device__ __align__(16) float g_qn[N * C];
__device__ __align__(16) float g_kn[N * C];

__global__ void zero_out_kernel(float* out) { out[0] = 0.0f; }

// One block per (batch b, 32-wide hw chunk): 4 * 32 = 128 blocks, 256 threads.
// Loads the C x 32 tile coalesced (hw fastest), computes per-hw-position
// channel L2 norm, writes normalized rows transposed: g_xn[n*C + c].
__global__ void normalize_kernel(const float* __restrict__ fq,
                                 const float* __restrict__ fk) {
    __shared__ float s[C][33];     // padded: conflict-free both directions
    __shared__ float ps[8][32];
    __shared__ float inv[32];

    const int b   = blockIdx.x >> 5;
    const int hw0 = (blockIdx.x & 31) << 5;
    const int t   = threadIdx.x;

    const float* srcs[2] = { fq, fk };
    float*       dsts[2] = { g_qn, g_kn };

    for (int p = 0; p < 2; p++) {
        const float* src = srcs[p] + (size_t)b * C * HW + hw0;

        // Load tile: e = c*32 + i ; consecutive threads -> consecutive hw (coalesced)
        #pragma unroll
        for (int iter = 0; iter < 16; iter++) {
            int e = t + iter * 256;
            int c = e >> 5, i = e & 31;
            s[c][i] = src[c * HW + i];
        }
        __syncthreads();

        // Sum of squares over channels for each of the 32 hw positions
        {
            int i = t & 31, c0 = t >> 5;
            float acc = 0.0f;
            #pragma unroll
            for (int c = c0; c < C; c += 8) { float v = s[c][i]; acc += v * v; }
            ps[c0][i] = acc;
        }
        __syncthreads();
        if (t < 32) {
            float sum = 0.0f;
            #pragma unroll
            for (int r = 0; r < 8; r++) sum += ps[r][t];
            inv[t] = 1.0f / fmaxf(sqrtf(sum), 1e-12f);
        }
        __syncthreads();

        // Write transposed normalized rows: e = i*128 + c ; consecutive threads
        // -> consecutive c (coalesced 512B rows). Shared read banks (c+i)%32: clean.
        float* dst = dsts[p] + ((size_t)b * HW + hw0) * C;
        #pragma unroll
        for (int iter = 0; iter < 16; iter++) {
            int e  = t + iter * 256;
            int ii = e >> 7, c = e & 127;
            dst[ii * C + c] = s[c][ii] * inv[ii];
        }
        __syncthreads();
    }
}

// One block (256 thr, 8 warps) per query row n. 129 warp-level dot products
// (1 positive + 128 gathered negatives), then logsumexp + atomic accumulate.
__global__ void pnce_kernel(const int* __restrict__ negi,
                            float* __restrict__ out) {
    __shared__ __align__(16) float sq[C];
    __shared__ float logits[129];

    const int n    = blockIdx.x;
    const int t    = threadIdx.x;
    const int w    = t >> 5;
    const int lane = t & 31;

    if (t < C) sq[t] = g_qn[n * C + t];
    __syncthreads();

    const float4 q4 = reinterpret_cast<const float4*>(sq)[lane];

    for (int j = w; j < 129; j += 8) {
        const int idx = (j == 0) ? n : negi[n * K + (j - 1)];
        const float4 k4 =
            reinterpret_cast<const float4*>(g_kn + (size_t)idx * C)[lane];
        float p = q4.x * k4.x + q4.y * k4.y + q4.z * k4.z + q4.w * k4.w;
        p += __shfl_xor_sync(0xffffffffu, p, 16);
        p += __shfl_xor_sync(0xffffffffu, p, 8);
        p += __shfl_xor_sync(0xffffffffu, p, 4);
        p += __shfl_xor_sync(0xffffffffu, p, 2);
        p += __shfl_xor_sync(0xffffffffu, p, 1);
        if (lane == 0) logits[j] = p * INV_TEMP;
    }
    __syncthreads();

    if (w == 0) {
        float m = -1e30f;
        for (int j = lane; j < 129; j += 32) m = fmaxf(m, logits[j]);
        #pragma unroll
        for (int o = 16; o; o >>= 1)
            m = fmaxf(m, __shfl_xor_sync(0xffffffffu, m, o));

        float se = 0.0f;
        for (int j = lane; j < 129; j += 32) se += expf(logits[j] - m);
        #pragma unroll
        for (int o = 16; o; o >>= 1)
            se += __shfl_xor_sync(0xffffffffu, se, o);

        if (lane == 0) {
            float lse = m + logf(se);
            atomicAdd(out, (lse - logits[0]) * (1.0f / (float)N));
        }
    }
}

extern "C" void kernel_launch(void* const* d_in, const int* in_sizes, int n_in,
                              void* d_out, int out_size) {
    const float* feat_q = (const float*)d_in[0];
    const float* feat_k = (const float*)d_in[1];
    const int*   negi   = (const int*)d_in[2];
    float*       out    = (float*)d_out;

    zero_out_kernel<<<1, 1>>>(out);
    normalize_kernel<<<128, 256>>>(feat_q, feat_k);
    pnce_kernel<<<N, 256>>>(negi, out);
}

// round 5
// speedup vs baseline: 1.3302x; 1.3302x over previous
#include <cuda_runtime.h>
#include <cuda_fp16.h>
#include <math.h>

#define C   128
#define HW  1024
#define N   4096
#define K   128
#define INV_TEMP (1.0f/0.07f)

// Scratch: normalized row-major [N, C] features.
__device__ __align__(16) float  g_qn[N * C];   // fp32 queries (2 MB)
__device__ __align__(16) __half g_kh[N * C];   // fp16 keys    (1 MB, gather target)

// One block per (batch b, 32-wide hw chunk): 4 * 32 = 128 blocks, 256 threads.
// Normalizes over channels, writes transposed rows. Block 0 also zeroes out.
__global__ void normalize_kernel(const float* __restrict__ fq,
                                 const float* __restrict__ fk,
                                 float* __restrict__ out) {
    __shared__ float s[C][33];
    __shared__ float ps[8][32];
    __shared__ float inv[32];

    if (blockIdx.x == 0 && threadIdx.x == 0) out[0] = 0.0f;

    const int b   = blockIdx.x >> 5;
    const int hw0 = (blockIdx.x & 31) << 5;
    const int t   = threadIdx.x;

    for (int p = 0; p < 2; p++) {
        const float* src = (p == 0 ? fq : fk) + (size_t)b * C * HW + hw0;

        // Load C x 32 tile, hw fastest (coalesced)
        #pragma unroll
        for (int iter = 0; iter < 16; iter++) {
            int e = t + iter * 256;
            int c = e >> 5, i = e & 31;
            s[c][i] = src[c * HW + i];
        }
        __syncthreads();

        // Sum of squares over channels per hw position
        {
            int i = t & 31, c0 = t >> 5;
            float acc = 0.0f;
            #pragma unroll
            for (int c = c0; c < C; c += 8) { float v = s[c][i]; acc += v * v; }
            ps[c0][i] = acc;
        }
        __syncthreads();
        if (t < 32) {
            float sum = 0.0f;
            #pragma unroll
            for (int r = 0; r < 8; r++) sum += ps[r][t];
            inv[t] = 1.0f / fmaxf(sqrtf(sum), 1e-12f);
        }
        __syncthreads();

        // Write transposed normalized rows (coalesced over c)
        const size_t base = ((size_t)b * HW + hw0) * C;
        if (p == 0) {
            float* dst = g_qn + base;
            #pragma unroll
            for (int iter = 0; iter < 16; iter++) {
                int e  = t + iter * 256;
                int ii = e >> 7, c = e & 127;
                dst[ii * C + c] = s[c][ii] * inv[ii];
            }
        } else {
            __half* dst = g_kh + base;
            #pragma unroll
            for (int iter = 0; iter < 16; iter++) {
                int e  = t + iter * 256;
                int ii = e >> 7, c = e & 127;
                dst[ii * C + c] = __float2half(s[c][ii] * inv[ii]);
            }
        }
        __syncthreads();
    }
}

// Lane-local 4-element partial dot: q (fp32 x4) . k (fp16 x4)
__device__ __forceinline__ float dot4(float4 q, uint2 kv) {
    const float2 k0 = __half22float2(*reinterpret_cast<const __half2*>(&kv.x));
    const float2 k1 = __half22float2(*reinterpret_cast<const __half2*>(&kv.y));
    return q.x * k0.x + q.y * k0.y + q.z * k1.x + q.w * k1.y;
}

__device__ __forceinline__ float warp_sum(float p) {
    p += __shfl_xor_sync(0xffffffffu, p, 16);
    p += __shfl_xor_sync(0xffffffffu, p, 8);
    p += __shfl_xor_sync(0xffffffffu, p, 4);
    p += __shfl_xor_sync(0xffffffffu, p, 2);
    p += __shfl_xor_sync(0xffffffffu, p, 1);
    return p;
}

// One block (256 thr = 8 warps) per query row n. One WHOLE warp per dot:
// lane covers 4 channels (8 B of the 256 B fp16 row, coalesced LDG.64).
// All shfls are full-warp with warp-uniform trip counts -> no divergence,
// no sub-warp masks (the half-warp variants of this kernel hung).
__global__ void pnce_kernel(const int* __restrict__ negi,
                            float* __restrict__ out) {
    __shared__ __align__(16) float sq[C];
    __shared__ int   sneg[K];
    __shared__ float logits[129];

    const int n    = blockIdx.x;
    const int t    = threadIdx.x;
    const int w    = t >> 5;       // warp id 0..7
    const int lane = t & 31;

    if (t < C) sq[t] = g_qn[n * C + t];
    if (t < K) sneg[t] = negi[n * K + t];
    __syncthreads();

    const float4 q4 = reinterpret_cast<const float4*>(sq)[lane];

    // Pairs (j, j+8) per trip, stride 16: union covers {w + 8k}, and two
    // independent gather loads are in flight per warp. j is warp-uniform.
    for (int j = w; j < 129; j += 16) {
        const int j2 = j + 8;
        const int idx1 = (j == 0) ? n : sneg[j - 1];
        const uint2 kv1 =
            reinterpret_cast<const uint2*>(g_kh + (size_t)idx1 * C)[lane];

        if (j2 < 129) {
            const int idx2 = sneg[j2 - 1];
            const uint2 kv2 =
                reinterpret_cast<const uint2*>(g_kh + (size_t)idx2 * C)[lane];
            float p1 = warp_sum(dot4(q4, kv1));
            float p2 = warp_sum(dot4(q4, kv2));
            if (lane == 0) {
                logits[j]  = p1 * INV_TEMP;
                logits[j2] = p2 * INV_TEMP;
            }
        } else {
            float p1 = warp_sum(dot4(q4, kv1));
            if (lane == 0) logits[j] = p1 * INV_TEMP;
        }
    }
    __syncthreads();

    if (t < 32) {
        float m = -1e30f;
        for (int j = t; j < 129; j += 32) m = fmaxf(m, logits[j]);
        #pragma unroll
        for (int o = 16; o; o >>= 1)
            m = fmaxf(m, __shfl_xor_sync(0xffffffffu, m, o));

        float se = 0.0f;
        for (int j = t; j < 129; j += 32) se += expf(logits[j] - m);
        #pragma unroll
        for (int o = 16; o; o >>= 1)
            se += __shfl_xor_sync(0xffffffffu, se, o);

        if (t == 0) {
            float lse = m + logf(se);
            atomicAdd(out, (lse - logits[0]) * (1.0f / (float)N));
        }
    }
}

extern "C" void kernel_launch(void* const* d_in, const int* in_sizes, int n_in,
                              void* d_out, int out_size) {
    const float* feat_q = (const float*)d_in[0];
    const float* feat_k = (const float*)d_in[1];
    const int*   negi   = (const int*)d_in[2];
    float*       out    = (float*)d_out;

    normalize_kernel<<<128, 256>>>(feat_q, feat_k, out);
    pnce_kernel<<<N, 256>>>(negi, out);
}

// round 6
// speedup vs baseline: 1.6153x; 1.2143x over previous
#include <cuda_runtime.h>
#include <cuda_fp16.h>
#include <math.h>

#define C   128
#define HW  1024
#define N   4096
#define K   128
#define INV_TEMP (1.0f/0.07f)

// Scratch: normalized row-major [N, C] features.
__device__ __align__(16) float  g_qn[N * C];   // fp32 queries (2 MB)
__device__ __align__(16) __half g_kh[N * C];   // fp16 keys    (1 MB, gather target)

// One block per (batch b, 32-wide hw chunk): 4 * 32 = 128 blocks, 256 threads.
__global__ void normalize_kernel(const float* __restrict__ fq,
                                 const float* __restrict__ fk,
                                 float* __restrict__ out) {
    __shared__ float s[C][33];
    __shared__ float ps[8][32];
    __shared__ float inv[32];

    if (blockIdx.x == 0 && threadIdx.x == 0) out[0] = 0.0f;

    const int b   = blockIdx.x >> 5;
    const int hw0 = (blockIdx.x & 31) << 5;
    const int t   = threadIdx.x;

    for (int p = 0; p < 2; p++) {
        const float* src = (p == 0 ? fq : fk) + (size_t)b * C * HW + hw0;

        #pragma unroll
        for (int iter = 0; iter < 16; iter++) {
            int e = t + iter * 256;
            int c = e >> 5, i = e & 31;
            s[c][i] = src[c * HW + i];
        }
        __syncthreads();

        {
            int i = t & 31, c0 = t >> 5;
            float acc = 0.0f;
            #pragma unroll
            for (int c = c0; c < C; c += 8) { float v = s[c][i]; acc += v * v; }
            ps[c0][i] = acc;
        }
        __syncthreads();
        if (t < 32) {
            float sum = 0.0f;
            #pragma unroll
            for (int r = 0; r < 8; r++) sum += ps[r][t];
            inv[t] = 1.0f / fmaxf(sqrtf(sum), 1e-12f);
        }
        __syncthreads();

        const size_t base = ((size_t)b * HW + hw0) * C;
        if (p == 0) {
            float* dst = g_qn + base;
            #pragma unroll
            for (int iter = 0; iter < 16; iter++) {
                int e  = t + iter * 256;
                int ii = e >> 7, c = e & 127;
                dst[ii * C + c] = s[c][ii] * inv[ii];
            }
        } else {
            __half* dst = g_kh + base;
            #pragma unroll
            for (int iter = 0; iter < 16; iter++) {
                int e  = t + iter * 256;
                int ii = e >> 7, c = e & 127;
                dst[ii * C + c] = __float2half(s[c][ii] * inv[ii]);
            }
        }
        __syncthreads();
    }
}

// Lane-local 8-element partial dot: q (fp32 x8) . k (fp16 x8 in uint4)
__device__ __forceinline__ float dot8(float4 qa, float4 qb, uint4 kv) {
    const float2 k0 = __half22float2(*reinterpret_cast<const __half2*>(&kv.x));
    const float2 k1 = __half22float2(*reinterpret_cast<const __half2*>(&kv.y));
    const float2 k2 = __half22float2(*reinterpret_cast<const __half2*>(&kv.z));
    const float2 k3 = __half22float2(*reinterpret_cast<const __half2*>(&kv.w));
    return qa.x * k0.x + qa.y * k0.y + qa.z * k1.x + qa.w * k1.y
         + qb.x * k2.x + qb.y * k2.y + qb.z * k3.x + qb.w * k3.y;
}

// 16-lane-half reduction executed by the FULL converged warp: xor offsets
// 8/4/2/1 never cross the 16-lane boundary, so lanes 0 and 16 end with the
// sums of their own halves. Full mask, warp-uniform control flow throughout.
__device__ __forceinline__ float half_sum(float p) {
    p += __shfl_xor_sync(0xffffffffu, p, 8);
    p += __shfl_xor_sync(0xffffffffu, p, 4);
    p += __shfl_xor_sync(0xffffffffu, p, 2);
    p += __shfl_xor_sync(0xffffffffu, p, 1);
    return p;
}

// One block (256 thr = 8 warps) per query row n. Each warp computes TWO dots
// per load: lanes 0-15 cover row a, lanes 16-31 cover row b (LDG.128, 16 B
// per lane, 2 full 256 B rows per warp). 130 slots = 65 pairs (slot 129 is a
// dummy: idx=n, result discarded) -> no ragged tail, warp-uniform trips.
__global__ void pnce_kernel(const int* __restrict__ negi,
                            float* __restrict__ out) {
    __shared__ __align__(16) float sq[C];
    __shared__ int   sneg[K];
    __shared__ float logits[129];

    const int n    = blockIdx.x;
    const int t    = threadIdx.x;
    const int w    = t >> 5;        // warp id 0..7
    const int lane = t & 31;
    const int l    = lane & 15;     // lane within half
    const int half = lane >> 4;     // 0 or 1

    if (t < C) sq[t] = g_qn[n * C + t];
    if (t < K) sneg[t] = negi[n * K + t];
    __syncthreads();

    // This lane's 8 channels (same channel mapping in both halves)
    const float4 qa = reinterpret_cast<const float4*>(sq)[2 * l];
    const float4 qb = reinterpret_cast<const float4*>(sq)[2 * l + 1];

    // Pair p covers slots (2p, 2p+1). 65 pairs; 2 pairs in flight per trip.
    for (int p0 = w; p0 < 65; p0 += 16) {
        const int p1 = p0 + 8;

        const int j1   = 2 * p0 + half;
        const int idx1 = (j1 == 0) ? n : ((j1 < 129) ? sneg[j1 - 1] : n);
        const uint4 kv1 =
            reinterpret_cast<const uint4*>(g_kh + (size_t)idx1 * C)[l];

        if (p1 < 65) {
            const int j2   = 2 * p1 + half;
            const int idx2 = (j2 < 129) ? sneg[j2 - 1] : n;
            const uint4 kv2 =
                reinterpret_cast<const uint4*>(g_kh + (size_t)idx2 * C)[l];

            float s1 = half_sum(dot8(qa, qb, kv1));
            float s2 = half_sum(dot8(qa, qb, kv2));
            if (l == 0 && j1 < 129) logits[j1] = s1 * INV_TEMP;
            if (l == 0 && j2 < 129) logits[j2] = s2 * INV_TEMP;
        } else {
            float s1 = half_sum(dot8(qa, qb, kv1));
            if (l == 0 && j1 < 129) logits[j1] = s1 * INV_TEMP;
        }
    }
    __syncthreads();

    if (t < 32) {
        float m = -1e30f;
        for (int j = t; j < 129; j += 32) m = fmaxf(m, logits[j]);
        #pragma unroll
        for (int o = 16; o; o >>= 1)
            m = fmaxf(m, __shfl_xor_sync(0xffffffffu, m, o));

        float se = 0.0f;
        for (int j = t; j < 129; j += 32) se += expf(logits[j] - m);
        #pragma unroll
        for (int o = 16; o; o >>= 1)
            se += __shfl_xor_sync(0xffffffffu, se, o);

        if (t == 0) {
            float lse = m + logf(se);
            atomicAdd(out, (lse - logits[0]) * (1.0f / (float)N));
        }
    }
}

extern "C" void kernel_launch(void* const* d_in, const int* in_sizes, int n_in,
                              void* d_out, int out_size) {
    const float* feat_q = (const float*)d_in[0];
    const float* feat_k = (const float*)d_in[1];
    const int*   negi   = (const int*)d_in[2];
    float*       out    = (float*)d_out;

    normalize_kernel<<<128, 256>>>(feat_q, feat_k, out);
    pnce_kernel<<<N, 256>>>(negi, out);
}

// round 7
// speedup vs baseline: 1.6762x; 1.0377x over previous
#include <cuda_runtime.h>
#include <cuda_fp16.h>
#include <math.h>

#define C   128
#define HW  1024
#define N   4096
#define K   128
#define INV_TEMP (1.0f/0.07f)

// Scratch: normalized row-major [N, C] fp16 features (1 MB each).
__device__ __align__(16) __half g_qh[N * C];
__device__ __align__(16) __half g_kh[N * C];

// One block per (tensor p, batch b, 32-wide hw chunk): 2*4*32 = 256 blocks.
// Normalizes over channels, writes transposed fp16 rows. Block 0 zeroes out.
__global__ void normalize_kernel(const float* __restrict__ fq,
                                 const float* __restrict__ fk,
                                 float* __restrict__ out) {
    __shared__ float s[C][33];
    __shared__ float ps[8][32];
    __shared__ float inv[32];

    if (blockIdx.x == 0 && threadIdx.x == 0) out[0] = 0.0f;

    const int p   = blockIdx.x >> 7;          // 0 = q, 1 = k
    const int b   = (blockIdx.x >> 5) & 3;
    const int hw0 = (blockIdx.x & 31) << 5;
    const int t   = threadIdx.x;

    const float* src = (p == 0 ? fq : fk) + (size_t)b * C * HW + hw0;

    // Load C x 32 tile, hw fastest (coalesced)
    #pragma unroll
    for (int iter = 0; iter < 16; iter++) {
        int e = t + iter * 256;
        int c = e >> 5, i = e & 31;
        s[c][i] = src[c * HW + i];
    }
    __syncthreads();

    // Sum of squares over channels per hw position
    {
        int i = t & 31, c0 = t >> 5;
        float acc = 0.0f;
        #pragma unroll
        for (int c = c0; c < C; c += 8) { float v = s[c][i]; acc += v * v; }
        ps[c0][i] = acc;
    }
    __syncthreads();
    if (t < 32) {
        float sum = 0.0f;
        #pragma unroll
        for (int r = 0; r < 8; r++) sum += ps[r][t];
        inv[t] = 1.0f / fmaxf(sqrtf(sum), 1e-12f);
    }
    __syncthreads();

    // Write transposed normalized fp16 rows (coalesced over c)
    __half* dst = (p == 0 ? g_qh : g_kh) + ((size_t)b * HW + hw0) * C;
    #pragma unroll
    for (int iter = 0; iter < 16; iter++) {
        int e  = t + iter * 256;
        int ii = e >> 7, c = e & 127;
        dst[ii * C + c] = __float2half(s[c][ii] * inv[ii]);
    }
}

// Lane-local 8-element partial dot, all-fp16 HFMA2, fp32 at the end.
__device__ __forceinline__ float dot8h(__half2 q0, __half2 q1, __half2 q2,
                                       __half2 q3, uint4 kv) {
    __half2 acc = __hmul2(q0, *reinterpret_cast<const __half2*>(&kv.x));
    acc = __hfma2(q1, *reinterpret_cast<const __half2*>(&kv.y), acc);
    acc = __hfma2(q2, *reinterpret_cast<const __half2*>(&kv.z), acc);
    acc = __hfma2(q3, *reinterpret_cast<const __half2*>(&kv.w), acc);
    const float2 f = __half22float2(acc);
    return f.x + f.y;
}

// 16-lane-half reduction executed by the FULL converged warp: xor offsets
// 8/4/2/1 never cross the 16-lane boundary; lanes 0 and 16 end with the
// sums of their halves. Full mask, warp-uniform control flow throughout.
__device__ __forceinline__ float half_sum(float p) {
    p += __shfl_xor_sync(0xffffffffu, p, 8);
    p += __shfl_xor_sync(0xffffffffu, p, 4);
    p += __shfl_xor_sync(0xffffffffu, p, 2);
    p += __shfl_xor_sync(0xffffffffu, p, 1);
    return p;
}

// One block (256 thr = 8 warps) per query row n. Each warp computes TWO dots
// per LDG.128 (lanes 0-15 row a, lanes 16-31 row b; 16 B/lane = 2 full 256 B
// fp16 rows/warp). 130 slots = 65 pairs (slot 129 dummy) -> uniform trips.
__global__ void pnce_kernel(const int* __restrict__ negi,
                            float* __restrict__ out) {
    __shared__ int   sneg[K];
    __shared__ float logits[129];

    const int n    = blockIdx.x;
    const int t    = threadIdx.x;
    const int w    = t >> 5;        // warp id 0..7
    const int lane = t & 31;
    const int l    = lane & 15;     // lane within half
    const int half = lane >> 4;     // 0 or 1

    if (t < K) sneg[t] = negi[n * K + t];
    __syncthreads();

    // This lane's 8 query channels as 4 half2 (same mapping in both halves)
    const uint4 qv = reinterpret_cast<const uint4*>(g_qh + (size_t)n * C)[l];
    const __half2 q0 = *reinterpret_cast<const __half2*>(&qv.x);
    const __half2 q1 = *reinterpret_cast<const __half2*>(&qv.y);
    const __half2 q2 = *reinterpret_cast<const __half2*>(&qv.z);
    const __half2 q3 = *reinterpret_cast<const __half2*>(&qv.w);

    // Pair p covers slots (2p, 2p+1). 65 pairs; 2 pairs in flight per trip.
    for (int p0 = w; p0 < 65; p0 += 16) {
        const int p1 = p0 + 8;

        const int j1   = 2 * p0 + half;
        const int idx1 = (j1 == 0) ? n : ((j1 < 129) ? sneg[j1 - 1] : n);
        const uint4 kv1 =
            reinterpret_cast<const uint4*>(g_kh + (size_t)idx1 * C)[l];

        if (p1 < 65) {
            const int j2   = 2 * p1 + half;
            const int idx2 = (j2 < 129) ? sneg[j2 - 1] : n;
            const uint4 kv2 =
                reinterpret_cast<const uint4*>(g_kh + (size_t)idx2 * C)[l];

            float s1 = half_sum(dot8h(q0, q1, q2, q3, kv1));
            float s2 = half_sum(dot8h(q0, q1, q2, q3, kv2));
            if (l == 0 && j1 < 129) logits[j1] = s1 * INV_TEMP;
            if (l == 0 && j2 < 129) logits[j2] = s2 * INV_TEMP;
        } else {
            float s1 = half_sum(dot8h(q0, q1, q2, q3, kv1));
            if (l == 0 && j1 < 129) logits[j1] = s1 * INV_TEMP;
        }
    }
    __syncthreads();

    if (t < 32) {
        float m = -1e30f;
        for (int j = t; j < 129; j += 32) m = fmaxf(m, logits[j]);
        #pragma unroll
        for (int o = 16; o; o >>= 1)
            m = fmaxf(m, __shfl_xor_sync(0xffffffffu, m, o));

        float se = 0.0f;
        for (int j = t; j < 129; j += 32) se += expf(logits[j] - m);
        #pragma unroll
        for (int o = 16; o; o >>= 1)
            se += __shfl_xor_sync(0xffffffffu, se, o);

        if (t == 0) {
            float lse = m + logf(se);
            atomicAdd(out, (lse - logits[0]) * (1.0f / (float)N));
        }
    }
}

extern "C" void kernel_launch(void* const* d_in, const int* in_sizes, int n_in,
                              void* d_out, int out_size) {
    const float* feat_q = (const float*)d_in[0];
    const float* feat_k = (const float*)d_in[1];
    const int*   negi   = (const int*)d_in[2];
    float*       out    = (float*)d_out;

    normalize_kernel<<<256, 256>>>(feat_q, feat_k, out);
    pnce_kernel<<<N, 256>>>(negi, out);
}

// round 8
// speedup vs baseline: 1.7978x; 1.0725x over previous
#include <cuda_runtime.h>
#include <cuda_fp16.h>
#include <math.h>

#define C   128
#define HW  1024
#define N   4096
#define K   128
#define INV_TEMP (1.0f/0.07f)

// Scratch: normalized row-major [N, C] fp16 features (1 MB each).
__device__ __align__(16) __half g_qh[N * C];
__device__ __align__(16) __half g_kh[N * C];

// One block per (tensor p, batch b, 32-wide hw chunk): 2*4*32 = 256 blocks.
__global__ void normalize_kernel(const float* __restrict__ fq,
                                 const float* __restrict__ fk,
                                 float* __restrict__ out) {
    __shared__ float s[C][33];
    __shared__ float ps[8][32];
    __shared__ float inv[32];

    if (blockIdx.x == 0 && threadIdx.x == 0) out[0] = 0.0f;

    const int p   = blockIdx.x >> 7;          // 0 = q, 1 = k
    const int b   = (blockIdx.x >> 5) & 3;
    const int hw0 = (blockIdx.x & 31) << 5;
    const int t   = threadIdx.x;

    const float* src = (p == 0 ? fq : fk) + (size_t)b * C * HW + hw0;

    #pragma unroll
    for (int iter = 0; iter < 16; iter++) {
        int e = t + iter * 256;
        int c = e >> 5, i = e & 31;
        s[c][i] = src[c * HW + i];
    }
    __syncthreads();

    {
        int i = t & 31, c0 = t >> 5;
        float acc = 0.0f;
        #pragma unroll
        for (int c = c0; c < C; c += 8) { float v = s[c][i]; acc += v * v; }
        ps[c0][i] = acc;
    }
    __syncthreads();
    if (t < 32) {
        float sum = 0.0f;
        #pragma unroll
        for (int r = 0; r < 8; r++) sum += ps[r][t];
        inv[t] = 1.0f / fmaxf(sqrtf(sum), 1e-12f);
    }
    __syncthreads();

    __half* dst = (p == 0 ? g_qh : g_kh) + ((size_t)b * HW + hw0) * C;
    #pragma unroll
    for (int iter = 0; iter < 16; iter++) {
        int e  = t + iter * 256;
        int ii = e >> 7, c = e & 127;
        dst[ii * C + c] = __float2half(s[c][ii] * inv[ii]);
    }
}

// Lane-local 16-element partial dot: one HFMA2 chain over 8 half2, one convert.
__device__ __forceinline__ float dot16h(const uint4& qv0, const uint4& qv1,
                                        const uint4& kv0, const uint4& kv1) {
    const __half2* q = reinterpret_cast<const __half2*>(&qv0);
    const __half2* Q = reinterpret_cast<const __half2*>(&qv1);
    const __half2* k = reinterpret_cast<const __half2*>(&kv0);
    const __half2* Kk = reinterpret_cast<const __half2*>(&kv1);
    __half2 acc = __hmul2(q[0], k[0]);
    acc = __hfma2(q[1], k[1], acc);
    acc = __hfma2(q[2], k[2], acc);
    acc = __hfma2(q[3], k[3], acc);
    acc = __hfma2(Q[0], Kk[0], acc);
    acc = __hfma2(Q[1], Kk[1], acc);
    acc = __hfma2(Q[2], Kk[2], acc);
    acc = __hfma2(Q[3], Kk[3], acc);
    const float2 f = __half22float2(acc);
    return f.x + f.y;
}

// 8-lane-group reduction executed by the FULL converged warp: xor offsets
// 4/2/1 never cross the 8-lane boundary; lanes 0,8,16,24 end with their
// group sums. Full mask, warp-uniform control flow throughout.
__device__ __forceinline__ float group8_sum(float p) {
    p += __shfl_xor_sync(0xffffffffu, p, 4);
    p += __shfl_xor_sync(0xffffffffu, p, 2);
    p += __shfl_xor_sync(0xffffffffu, p, 1);
    return p;
}

// One block (256 thr = 8 warps) per query row n. Each warp computes FOUR dots
// per trip: lane group g (8 lanes) covers row slot j0+g; each lane holds 32 B
// of the row via two uint4 loads at [l8] and [l8+8] (each LDG = 4 rows x
// 128 B contiguous = 4 full lines). 3-step shfl reduce per 4 dots.
__global__ void pnce_kernel(const int* __restrict__ negi,
                            float* __restrict__ out) {
    __shared__ int   sneg[K];
    __shared__ float logits[129];

    const int n    = blockIdx.x;
    const int t    = threadIdx.x;
    const int w    = t >> 5;        // warp id 0..7
    const int lane = t & 31;
    const int g    = lane >> 3;     // group 0..3
    const int l8   = lane & 7;      // lane within group

    if (t < K) sneg[t] = negi[n * K + t];
    __syncthreads();

    // Query: lane's 16 channels (broadcast across groups/warps -> L1 hits)
    const uint4* qptr = reinterpret_cast<const uint4*>(g_qh + (size_t)n * C);
    const uint4 qv0 = qptr[l8];
    const uint4 qv1 = qptr[l8 + 8];

    // Slots: 0 = positive, 1..128 = negatives. j0 warp-uniform; dummies use
    // idx=n and are discarded. Two trips interleaved -> 4 gathers in flight.
    for (int j0 = 4 * w; j0 <= 128; j0 += 64) {
        const int j0b = j0 + 32;

        const int ja   = j0 + g;
        const int idxa = (ja == 0) ? n : ((ja <= 128) ? sneg[ja - 1] : n);
        const uint4* ka = reinterpret_cast<const uint4*>(g_kh + (size_t)idxa * C);
        const uint4 ka0 = ka[l8];
        const uint4 ka1 = ka[l8 + 8];

        if (j0b <= 128) {
            const int jb   = j0b + g;
            const int idxb = (jb <= 128) ? sneg[jb - 1] : n;
            const uint4* kb = reinterpret_cast<const uint4*>(g_kh + (size_t)idxb * C);
            const uint4 kb0 = kb[l8];
            const uint4 kb1 = kb[l8 + 8];

            float sa = group8_sum(dot16h(qv0, qv1, ka0, ka1));
            float sb = group8_sum(dot16h(qv0, qv1, kb0, kb1));
            if (l8 == 0 && ja <= 128) logits[ja] = sa * INV_TEMP;
            if (l8 == 0 && jb <= 128) logits[jb] = sb * INV_TEMP;
        } else {
            float sa = group8_sum(dot16h(qv0, qv1, ka0, ka1));
            if (l8 == 0 && ja <= 128) logits[ja] = sa * INV_TEMP;
        }
    }
    __syncthreads();

    if (t < 32) {
        float m = -1e30f;
        for (int j = t; j < 129; j += 32) m = fmaxf(m, logits[j]);
        #pragma unroll
        for (int o = 16; o; o >>= 1)
            m = fmaxf(m, __shfl_xor_sync(0xffffffffu, m, o));

        float se = 0.0f;
        for (int j = t; j < 129; j += 32) se += expf(logits[j] - m);
        #pragma unroll
        for (int o = 16; o; o >>= 1)
            se += __shfl_xor_sync(0xffffffffu, se, o);

        if (t == 0) {
            float lse = m + logf(se);
            atomicAdd(out, (lse - logits[0]) * (1.0f / (float)N));
        }
    }
}

extern "C" void kernel_launch(void* const* d_in, const int* in_sizes, int n_in,
                              void* d_out, int out_size) {
    const float* feat_q = (const float*)d_in[0];
    const float* feat_k = (const float*)d_in[1];
    const int*   negi   = (const int*)d_in[2];
    float*       out    = (float*)d_out;

    normalize_kernel<<<256, 256>>>(feat_q, feat_k, out);
    pnce_kernel<<<N, 256>>>(negi, out);
}